// round 10
// baseline (speedup 1.0000x reference)
#include <cuda_runtime.h>
#include <cuda_fp16.h>
#include <math.h>

#define NA 900
#define NC 6
#define NL 4
#define NPTS 13
#define ED 256
#define NG 8
#define SS (NC*NL*NPTS)   /* 312 */
#define JJ (NL*NPTS*NG)   /* 416 */

// pixels per cam per level: 64*176=11264, 32*88=2816, 16*44=704, 8*22=176
// cam-major-within-level pixel bases: 0, 67584, 84480, 88704 ; total 89760
#define TOT_PIX 89760

// ---------------- scratch (device globals; no runtime allocation) ----------------
__device__ __half  g_fmapT[TOT_PIX * ED];      // ~46 MB channel-last fp16 feature cache
__device__ float   g_B[NC * JJ];               // cam_embed @ wfc_w + b
__device__ float   g_A[NA * JJ];               // feat @ wfc_w
__device__ int4    g_ci[NA * SS];              // compacted corner element indices
__device__ float4  g_cv[NA * SS];              // compacted corner bilinear weights
__device__ int     g_cs[NA * SS];              // compacted original sample index
__device__ int     g_cnt[NA];                  // compacted count per anchor
__device__ float   g_fused[NA * ED];           // fused features pre-GEMM

// ---------------- kernel 1: unified transpose, all levels in one launch ------------
__global__ void k_transpose(const float* __restrict__ f0, const float* __restrict__ f1,
                            const float* __restrict__ f2, const float* __restrict__ f3) {
    __shared__ float tile[32][33];
    int pb = blockIdx.x;
    const float* src; int P, basePix;
    if (pb < 352)      { src = f0; P = 11264; basePix = 0; }
    else if (pb < 440) { src = f1; P = 2816;  basePix = 67584; pb -= 352; }
    else if (pb < 462) { src = f2; P = 704;   basePix = 84480; pb -= 440; }
    else               { src = f3; P = 176;   basePix = 88704; pb -= 462; }
    int cam = blockIdx.z;
    int p0 = pb * 32;
    int d0 = blockIdx.y * 32;
    int tx = threadIdx.x, ty = threadIdx.y;
#pragma unroll
    for (int i = ty; i < 32; i += 8) {
        int p = p0 + tx;
        if (p < P) tile[i][tx] = src[((size_t)cam * ED + d0 + i) * P + p];
    }
    __syncthreads();
#pragma unroll
    for (int i = ty; i < 32; i += 8) {
        int p = p0 + i;
        if (p < P)
            g_fmapT[((size_t)(basePix + cam * P + p)) * ED + d0 + tx] =
                __float2half_rn(tile[tx][i]);
    }
}

// ---------------- LN helper (256 threads) ----------------
__device__ __forceinline__ float ln256(float x, float g, float b, float* red) {
    float s = x;
#pragma unroll
    for (int o = 16; o > 0; o >>= 1) s += __shfl_xor_sync(0xffffffffu, s, o);
    if ((threadIdx.x & 31) == 0) red[threadIdx.x >> 5] = s;
    __syncthreads();
    if (threadIdx.x == 0) { float t = 0.f; for (int i = 0; i < 8; i++) t += red[i]; red[0] = t; }
    __syncthreads();
    float mean = red[0] * (1.f / 256.f);
    __syncthreads();
    float d = x - mean;
    float q = d * d;
#pragma unroll
    for (int o = 16; o > 0; o >>= 1) q += __shfl_xor_sync(0xffffffffu, q, o);
    if ((threadIdx.x & 31) == 0) red[threadIdx.x >> 5] = q;
    __syncthreads();
    if (threadIdx.x == 0) { float t = 0.f; for (int i = 0; i < 8; i++) t += red[i]; red[0] = t; }
    __syncthreads();
    float var = red[0] * (1.f / 256.f);
    float r = d * rsqrtf(var + 1e-5f) * g + b;
    __syncthreads();
    return r;
}

// ------- kernel 2: camera MLP + B[c] = cam_embed[c] @ wfc_w + b (6 blocks x 256) ----
__global__ void k_cam(const float* __restrict__ proj,
                      const float* __restrict__ w1, const float* __restrict__ b1,
                      const float* __restrict__ g1, const float* __restrict__ be1,
                      const float* __restrict__ w2, const float* __restrict__ b2,
                      const float* __restrict__ g2, const float* __restrict__ be2,
                      const float* __restrict__ wfcw, const float* __restrict__ wfcb) {
    int c = blockIdx.x, j = threadIdx.x;
    __shared__ float cin[12];
    __shared__ float h[ED];
    __shared__ float ce[ED];
    __shared__ float red[8];
    if (j < 12) cin[j] = proj[c * 16 + j];
    __syncthreads();
    float v = b1[j];
#pragma unroll
    for (int k = 0; k < 12; k++) v = fmaf(cin[k], w1[k * ED + j], v);
    v = fmaxf(v, 0.f);
    v = ln256(v, g1[j], be1[j], red);
    h[j] = v;
    __syncthreads();
    float u = b2[j];
#pragma unroll 8
    for (int k = 0; k < ED; k++) u = fmaf(h[k], w2[k * ED + j], u);
    u = fmaxf(u, 0.f);
    u = ln256(u, g2[j], be2[j], red);
    ce[j] = u;
    __syncthreads();
    for (int jj = j; jj < JJ; jj += 256) {
        float b = wfcb[jj];
#pragma unroll 8
        for (int k = 0; k < ED; k++) b = fmaf(ce[k], wfcw[k * JJ + jj], b);
        g_B[c * JJ + jj] = b;
    }
}

// ------- kernel 3: keypoints + projection + sample params + compaction --------------
__global__ void __launch_bounds__(256) k_keyproj(
        const float* __restrict__ inst, const float* __restrict__ anchor,
        const float* __restrict__ lfcw, const float* __restrict__ lfcb,
        const float* __restrict__ proj, const float* __restrict__ imwh,
        const float* __restrict__ fixs) {
    int n = blockIdx.x, t = threadIdx.x;
    int wid = t >> 5, lane = t & 31;
    __shared__ float f[ED];
    __shared__ float ls[18];
    __shared__ float kp[13][3];
    __shared__ float anc[11];
    __shared__ float grid[NC * NPTS][2];
    __shared__ int4  t_i[SS];
    __shared__ float4 t_v[SS];
    __shared__ unsigned char fl[SS];
    __shared__ short pos[SS];
    f[t] = inst[n * ED + t];
    if (t < 11) anc[t] = anchor[n * 11 + t];
    __syncthreads();
    // warp-parallel 18-output GEMV: warp w handles outputs w, w+8, w+16
    for (int o = wid; o < 18; o += 8) {
        float v = 0.f;
#pragma unroll
        for (int k = lane; k < ED; k += 32) v = fmaf(f[k], lfcw[k * 18 + o], v);
#pragma unroll
        for (int off = 16; off > 0; off >>= 1) v += __shfl_xor_sync(0xffffffffu, v, off);
        if (lane == 0) ls[o] = 1.f / (1.f + expf(-(v + lfcb[o]))) - 0.5f;
    }
    __syncthreads();
    if (t < 13) {
        float sx = expf(anc[3]), sy = expf(anc[4]), sz = expf(anc[5]);
        float kx, ky, kz;
        if (t < 7) { kx = fixs[t * 3] * sx; ky = fixs[t * 3 + 1] * sy; kz = fixs[t * 3 + 2] * sz; }
        else { int r = t - 7; kx = ls[r * 3] * sx; ky = ls[r * 3 + 1] * sy; kz = ls[r * 3 + 2] * sz; }
        float sn = anc[6], cs = anc[7];
        kp[t][0] = cs * kx - sn * ky + anc[0];
        kp[t][1] = sn * kx + cs * ky + anc[1];
        kp[t][2] = kz + anc[2];
    }
    __syncthreads();
    if (t < NC * NPTS) {
        int c = t / NPTS, p = t % NPTS;
        const float* P = proj + c * 16;
        float x = kp[p][0], y = kp[p][1], z = kp[p][2];
        float r0 = P[0] * x + P[1] * y + P[2] * z + P[3];
        float r1 = P[4] * x + P[5] * y + P[6] * z + P[7];
        float r2 = P[8] * x + P[9] * y + P[10] * z + P[11];
        float zz = fmaxf(r2, 1e-5f);
        grid[t][0] = (r0 / zz) / imwh[c * 2] * 2.f - 1.f;
        grid[t][1] = (r1 / zz) / imwh[c * 2 + 1] * 2.f - 1.f;
    }
    __syncthreads();
    const int Hs[4] = {64, 32, 16, 8}, Ws[4] = {176, 88, 44, 22};
    const int base[4] = {0, 67584, 84480, 88704};
    for (int s = t; s < SS; s += 256) {
        int c = s / (NL * NPTS); int r = s - c * (NL * NPTS);
        int l = r / NPTS, p = r - l * NPTS;
        float gxn = grid[c * NPTS + p][0];
        float gyn = grid[c * NPTS + p][1];
        int H = Hs[l], W = Ws[l];
        float gx = fminf(fmaxf((gxn + 1.f) * (W * 0.5f) - 0.5f, -10000.f), 10000.f);
        float gy = fminf(fmaxf((gyn + 1.f) * (H * 0.5f) - 0.5f, -10000.f), 10000.f);
        float x0f = floorf(gx), y0f = floorf(gy);
        float wx1 = gx - x0f, wy1 = gy - y0f;
        float wx0 = 1.f - wx1, wy0 = 1.f - wy1;
        int x0 = (int)x0f, y0 = (int)y0f;
        int x1 = x0 + 1, y1 = y0 + 1;
        bool vx0 = (x0 >= 0 && x0 < W), vx1 = (x1 >= 0 && x1 < W);
        bool vy0 = (y0 >= 0 && y0 < H), vy1 = (y1 >= 0 && y1 < H);
        int cx0 = min(max(x0, 0), W - 1), cx1 = min(max(x1, 0), W - 1);
        int cy0 = min(max(y0, 0), H - 1), cy1 = min(max(y1, 0), H - 1);
        int pb = base[l] + c * H * W;
        int4 ii;
        ii.x = (pb + cy0 * W + cx0) * ED;
        ii.y = (pb + cy0 * W + cx1) * ED;
        ii.z = (pb + cy1 * W + cx0) * ED;
        ii.w = (pb + cy1 * W + cx1) * ED;
        float4 ww;
        ww.x = wx0 * wy0 * (float)(vx0 && vy0);
        ww.y = wx1 * wy0 * (float)(vx1 && vy0);
        ww.z = wx0 * wy1 * (float)(vx0 && vy1);
        ww.w = wx1 * wy1 * (float)(vx1 && vy1);
        t_i[s] = ii;
        t_v[s] = ww;
        fl[s] = (ww.x + ww.y + ww.z + ww.w) > 0.f ? 1 : 0;
    }
    __syncthreads();
    // deterministic exclusive scan of flags (warp 0, 10 chunks of 32)
    if (t < 32) {
        int run = 0;
        for (int c0 = 0; c0 < SS; c0 += 32) {
            int s = c0 + t;
            int fv = (s < SS) ? (int)fl[s] : 0;
            int x = fv;
#pragma unroll
            for (int o = 1; o < 32; o <<= 1) {
                int y = __shfl_up_sync(0xffffffffu, x, o);
                if (t >= o) x += y;
            }
            if (s < SS) pos[s] = (short)(run + x - fv);
            run += __shfl_sync(0xffffffffu, x, 31);
        }
        if (t == 0) g_cnt[n] = run;
    }
    __syncthreads();
    for (int s = t; s < SS; s += 256) {
        if (fl[s]) {
            int p = pos[s];
            g_ci[n * SS + p] = t_i[s];
            g_cv[n * SS + p] = t_v[s];
            g_cs[n * SS + p] = s;
        }
    }
}

// ------- kernel 4: A[n][j] = (inst+anchor_embed)[n] @ wfc_w  grid(90,2) x 208 -------
#define AB 10
#define JT 208
__global__ void __launch_bounds__(JT) k_A(const float* __restrict__ inst,
                                          const float* __restrict__ aemb,
                                          const float* __restrict__ wfcw) {
    int n0 = blockIdx.x * AB;
    int t = threadIdx.x;
    int j = blockIdx.y * JT + t;
    __shared__ float fs[AB][ED];
    for (int i = t; i < AB * ED; i += JT) {
        int a = i >> 8, k = i & 255;
        fs[a][k] = inst[(n0 + a) * ED + k] + aemb[(n0 + a) * ED + k];
    }
    __syncthreads();
    float acc[AB];
#pragma unroll
    for (int a = 0; a < AB; a++) acc[a] = 0.f;
    for (int k = 0; k < ED; k += 4) {
        float w0 = wfcw[(k + 0) * JJ + j];
        float w1 = wfcw[(k + 1) * JJ + j];
        float w2 = wfcw[(k + 2) * JJ + j];
        float w3 = wfcw[(k + 3) * JJ + j];
#pragma unroll
        for (int a = 0; a < AB; a++) {
            float4 f = *(const float4*)&fs[a][k];
            acc[a] = fmaf(f.x, w0, acc[a]);
            acc[a] = fmaf(f.y, w1, acc[a]);
            acc[a] = fmaf(f.z, w2, acc[a]);
            acc[a] = fmaf(f.w, w3, acc[a]);
        }
    }
#pragma unroll
    for (int a = 0; a < AB; a++) g_A[(n0 + a) * JJ + j] = acc[a];
}

// ------- kernel 5: softmax + warp-per-sample fp16 gather (900 blocks x 256) ---------
__global__ void __launch_bounds__(256) k_fuse(const float* __restrict__ inst,
                                              float* __restrict__ out) {
    int n = blockIdx.x, t = threadIdx.x;
    int wid = t >> 5, lane = t & 31;
    __shared__ float  s_A[JJ];
    __shared__ float  s_B[NC * JJ];
    __shared__ float  s_w[SS * NG];
    __shared__ float  s_cw[SS * NG];
    __shared__ int4   s_ci[SS];
    __shared__ float4 s_cv[SS];
    __shared__ int    s_cs[SS];
    __shared__ float  s_acc[8][ED];
    __shared__ int    s_cnt;
    if (t == 0) s_cnt = g_cnt[n];
    for (int i = t; i < JJ; i += 256) s_A[i] = g_A[n * JJ + i];
    for (int i = t; i < NC * JJ; i += 256) s_B[i] = g_B[i];
    __syncthreads();
    int cnt = s_cnt;
    for (int i = t; i < cnt; i += 256) {
        s_ci[i] = g_ci[n * SS + i];
        s_cv[i] = g_cv[n * SS + i];
        s_cs[i] = g_cs[n * SS + i];
    }

    // --- softmax over 312 samples per group (warp g = group g) ---
    {
        int g = wid;
        float v[10];
        float mx = -1e30f;
#pragma unroll
        for (int i = 0; i < 10; i++) {
            int s = lane + i * 32;
            if (s < SS) {
                int c = s / (NL * NPTS); int r = s - c * (NL * NPTS);
                float val = s_A[r * 8 + g] + s_B[c * JJ + r * 8 + g];
                v[i] = val; mx = fmaxf(mx, val);
            } else v[i] = -1e30f;
        }
#pragma unroll
        for (int o = 16; o > 0; o >>= 1) mx = fmaxf(mx, __shfl_xor_sync(0xffffffffu, mx, o));
        float sum = 0.f;
#pragma unroll
        for (int i = 0; i < 10; i++) {
            v[i] = expf(v[i] - mx);
            if (lane + i * 32 < SS) sum += v[i];
        }
#pragma unroll
        for (int o = 16; o > 0; o >>= 1) sum += __shfl_xor_sync(0xffffffffu, sum, o);
        float inv = 1.f / sum;
#pragma unroll
        for (int i = 0; i < 10; i++) {
            int s = lane + i * 32;
            if (s < SS) s_w[s * NG + g] = v[i] * inv;
        }
    }
    __syncthreads();
    // pre-resolve compacted weights: s_cw[i*NG+g] = s_w[s_cs[i]*NG+g]
    for (int x = t; x < cnt * NG; x += 256) {
        int i = x >> 3, g = x & 7;
        s_cw[x] = s_w[s_cs[i] * NG + g];
    }
    __syncthreads();

    // --- gather: warp w handles compact samples w, w+8, ...; lane = 8 channels ------
    float acc0 = 0.f, acc1 = 0.f, acc2 = 0.f, acc3 = 0.f;
    float acc4 = 0.f, acc5 = 0.f, acc6 = 0.f, acc7 = 0.f;
    int grp = lane >> 2;
    for (int k2 = wid; k2 < cnt; k2 += 8) {
        int4 ii = s_ci[k2];
        float4 ww = s_cv[k2];
        float w = s_cw[k2 * NG + grp];
        float wa = w * ww.x, wb = w * ww.y, wc = w * ww.z, wd = w * ww.w;
        uint4 ua = *((const uint4*)(g_fmapT + ii.x) + lane);
        uint4 ub = *((const uint4*)(g_fmapT + ii.y) + lane);
        uint4 uc = *((const uint4*)(g_fmapT + ii.z) + lane);
        uint4 ud = *((const uint4*)(g_fmapT + ii.w) + lane);
        const __half2* ha = (const __half2*)&ua;
        const __half2* hb = (const __half2*)&ub;
        const __half2* hc = (const __half2*)&uc;
        const __half2* hd = (const __half2*)&ud;
        float2 a0 = __half22float2(ha[0]), a1 = __half22float2(ha[1]);
        float2 a2 = __half22float2(ha[2]), a3 = __half22float2(ha[3]);
        float2 b0 = __half22float2(hb[0]), b1 = __half22float2(hb[1]);
        float2 b2 = __half22float2(hb[2]), b3 = __half22float2(hb[3]);
        float2 c0 = __half22float2(hc[0]), c1 = __half22float2(hc[1]);
        float2 c2 = __half22float2(hc[2]), c3 = __half22float2(hc[3]);
        float2 d0 = __half22float2(hd[0]), d1 = __half22float2(hd[1]);
        float2 d2 = __half22float2(hd[2]), d3 = __half22float2(hd[3]);
        acc0 = fmaf(wa, a0.x, acc0); acc0 = fmaf(wb, b0.x, acc0); acc0 = fmaf(wc, c0.x, acc0); acc0 = fmaf(wd, d0.x, acc0);
        acc1 = fmaf(wa, a0.y, acc1); acc1 = fmaf(wb, b0.y, acc1); acc1 = fmaf(wc, c0.y, acc1); acc1 = fmaf(wd, d0.y, acc1);
        acc2 = fmaf(wa, a1.x, acc2); acc2 = fmaf(wb, b1.x, acc2); acc2 = fmaf(wc, c1.x, acc2); acc2 = fmaf(wd, d1.x, acc2);
        acc3 = fmaf(wa, a1.y, acc3); acc3 = fmaf(wb, b1.y, acc3); acc3 = fmaf(wc, c1.y, acc3); acc3 = fmaf(wd, d1.y, acc3);
        acc4 = fmaf(wa, a2.x, acc4); acc4 = fmaf(wb, b2.x, acc4); acc4 = fmaf(wc, c2.x, acc4); acc4 = fmaf(wd, d2.x, acc4);
        acc5 = fmaf(wa, a2.y, acc5); acc5 = fmaf(wb, b2.y, acc5); acc5 = fmaf(wc, c2.y, acc5); acc5 = fmaf(wd, d2.y, acc5);
        acc6 = fmaf(wa, a3.x, acc6); acc6 = fmaf(wb, b3.x, acc6); acc6 = fmaf(wc, c3.x, acc6); acc6 = fmaf(wd, d3.x, acc6);
        acc7 = fmaf(wa, a3.y, acc7); acc7 = fmaf(wb, b3.y, acc7); acc7 = fmaf(wc, c3.y, acc7); acc7 = fmaf(wd, d3.y, acc7);
    }
    {
        float4* dst = (float4*)&s_acc[wid][lane * 8];
        dst[0] = make_float4(acc0, acc1, acc2, acc3);
        dst[1] = make_float4(acc4, acc5, acc6, acc7);
    }
    __syncthreads();
    float fs = 0.f;
#pragma unroll
    for (int w = 0; w < 8; w++) fs += s_acc[w][t];
    g_fused[n * ED + t] = fs;
    out[(size_t)n * 2 * ED + ED + t] = inst[n * ED + t];
}

// ------- kernel 6: batched output GEMM  grid(75,2) x 128, 12 anchors each ----------
#define OB 12
#define OT 128
__global__ void __launch_bounds__(OT) k_out(const float* __restrict__ opw,
                                            const float* __restrict__ opb,
                                            float* __restrict__ out) {
    int n0 = blockIdx.x * OB;
    int t = threadIdx.x;
    int j = blockIdx.y * OT + t;
    __shared__ float fs[OB][ED];
    for (int i = t; i < OB * ED; i += OT) {
        int a = i >> 8, k = i & 255;
        fs[a][k] = g_fused[(n0 + a) * ED + k];
    }
    __syncthreads();
    float acc[OB];
    float bj = opb[j];
#pragma unroll
    for (int a = 0; a < OB; a++) acc[a] = bj;
    for (int k = 0; k < ED; k += 4) {
        float w0 = opw[(k + 0) * ED + j];
        float w1 = opw[(k + 1) * ED + j];
        float w2 = opw[(k + 2) * ED + j];
        float w3 = opw[(k + 3) * ED + j];
#pragma unroll
        for (int a = 0; a < OB; a++) {
            float4 f = *(const float4*)&fs[a][k];
            acc[a] = fmaf(f.x, w0, acc[a]);
            acc[a] = fmaf(f.y, w1, acc[a]);
            acc[a] = fmaf(f.z, w2, acc[a]);
            acc[a] = fmaf(f.w, w3, acc[a]);
        }
    }
#pragma unroll
    for (int a = 0; a < OB; a++) out[(size_t)(n0 + a) * 2 * ED + j] = acc[a];
}

// ---------------- launch ----------------
extern "C" void kernel_launch(void* const* d_in, const int* in_sizes, int n_in,
                              void* d_out, int out_size) {
    const float* inst  = (const float*)d_in[0];
    const float* anch  = (const float*)d_in[1];
    const float* aemb  = (const float*)d_in[2];
    const float* fm0   = (const float*)d_in[3];
    const float* fm1   = (const float*)d_in[4];
    const float* fm2   = (const float*)d_in[5];
    const float* fm3   = (const float*)d_in[6];
    const float* proj  = (const float*)d_in[7];
    const float* imwh  = (const float*)d_in[8];
    const float* fixs  = (const float*)d_in[9];
    const float* lfcw  = (const float*)d_in[10];
    const float* lfcb  = (const float*)d_in[11];
    const float* cw1   = (const float*)d_in[12];
    const float* cb1   = (const float*)d_in[13];
    const float* cg1   = (const float*)d_in[14];
    const float* cbe1  = (const float*)d_in[15];
    const float* cw2   = (const float*)d_in[16];
    const float* cb2   = (const float*)d_in[17];
    const float* cg2   = (const float*)d_in[18];
    const float* cbe2  = (const float*)d_in[19];
    const float* wfcw  = (const float*)d_in[20];
    const float* wfcb  = (const float*)d_in[21];
    const float* opw   = (const float*)d_in[22];
    const float* opb   = (const float*)d_in[23];
    float* out = (float*)d_out;

    k_transpose<<<dim3(468, 8, 6), dim3(32, 8)>>>(fm0, fm1, fm2, fm3);
    k_cam<<<NC, 256>>>(proj, cw1, cb1, cg1, cbe1, cw2, cb2, cg2, cbe2, wfcw, wfcb);
    k_keyproj<<<NA, 256>>>(inst, anch, lfcw, lfcb, proj, imwh, fixs);
    k_A<<<dim3(NA / AB, 2), JT>>>(inst, aemb, wfcw);
    k_fuse<<<NA, 256>>>(inst, out);
    k_out<<<dim3(NA / OB, 2), OT>>>(opw, opb, out);
}

// round 14
// speedup vs baseline: 1.0707x; 1.0707x over previous
#include <cuda_runtime.h>
#include <cuda_fp16.h>
#include <math.h>

#define NA 900
#define NC 6
#define NL 4
#define NPTS 13
#define ED 256
#define NG 8
#define SS (NC*NL*NPTS)   /* 312 */
#define JJ (NL*NPTS*NG)   /* 416 */

// pixels per cam per level: 64*176=11264, 32*88=2816, 16*44=704, 8*22=176
// cam-major-within-level pixel bases: 0, 67584, 84480, 88704 ; total 89760
#define TOT_PIX 89760

// ---------------- scratch (device globals; no runtime allocation) ----------------
__device__ __half  g_fmapT[TOT_PIX * ED];      // ~46 MB channel-last fp16 feature cache
__device__ float   g_B[NC * JJ];               // cam_embed @ wfc_w + b
__device__ float   g_A[NA * JJ];               // feat @ wfc_w
__device__ int4    g_ci[NA * SS];              // compacted corner element indices
__device__ float4  g_cv[NA * SS];              // compacted corner bilinear weights
__device__ int     g_cs[NA * SS];              // compacted original sample index
__device__ int     g_cnt[NA];                  // compacted count per anchor
__device__ float   g_fused[NA * ED];           // fused features pre-GEMM

// ---------------- kernel 1: unified transpose, all levels in one launch ------------
__global__ void k_transpose(const float* __restrict__ f0, const float* __restrict__ f1,
                            const float* __restrict__ f2, const float* __restrict__ f3) {
    __shared__ float tile[32][33];
    int pb = blockIdx.x;
    const float* src; int P, basePix;
    if (pb < 352)      { src = f0; P = 11264; basePix = 0; }
    else if (pb < 440) { src = f1; P = 2816;  basePix = 67584; pb -= 352; }
    else if (pb < 462) { src = f2; P = 704;   basePix = 84480; pb -= 440; }
    else               { src = f3; P = 176;   basePix = 88704; pb -= 462; }
    int cam = blockIdx.z;
    int p0 = pb * 32;
    int d0 = blockIdx.y * 32;
    int tx = threadIdx.x, ty = threadIdx.y;
#pragma unroll
    for (int i = ty; i < 32; i += 8) {
        int p = p0 + tx;
        if (p < P) tile[i][tx] = src[((size_t)cam * ED + d0 + i) * P + p];
    }
    __syncthreads();
#pragma unroll
    for (int i = ty; i < 32; i += 8) {
        int p = p0 + i;
        if (p < P)
            g_fmapT[((size_t)(basePix + cam * P + p)) * ED + d0 + tx] =
                __float2half_rn(tile[tx][i]);
    }
}

// ---------------- LN helper (256 threads) ----------------
__device__ __forceinline__ float ln256(float x, float g, float b, float* red) {
    float s = x;
#pragma unroll
    for (int o = 16; o > 0; o >>= 1) s += __shfl_xor_sync(0xffffffffu, s, o);
    if ((threadIdx.x & 31) == 0) red[threadIdx.x >> 5] = s;
    __syncthreads();
    if (threadIdx.x == 0) { float t = 0.f; for (int i = 0; i < 8; i++) t += red[i]; red[0] = t; }
    __syncthreads();
    float mean = red[0] * (1.f / 256.f);
    __syncthreads();
    float d = x - mean;
    float q = d * d;
#pragma unroll
    for (int o = 16; o > 0; o >>= 1) q += __shfl_xor_sync(0xffffffffu, q, o);
    if ((threadIdx.x & 31) == 0) red[threadIdx.x >> 5] = q;
    __syncthreads();
    if (threadIdx.x == 0) { float t = 0.f; for (int i = 0; i < 8; i++) t += red[i]; red[0] = t; }
    __syncthreads();
    float var = red[0] * (1.f / 256.f);
    float r = d * rsqrtf(var + 1e-5f) * g + b;
    __syncthreads();
    return r;
}

// ------- kernel 2: camera MLP + B[c] = cam_embed[c] @ wfc_w + b (6 blocks x 256) ----
__global__ void k_cam(const float* __restrict__ proj,
                      const float* __restrict__ w1, const float* __restrict__ b1,
                      const float* __restrict__ g1, const float* __restrict__ be1,
                      const float* __restrict__ w2, const float* __restrict__ b2,
                      const float* __restrict__ g2, const float* __restrict__ be2,
                      const float* __restrict__ wfcw, const float* __restrict__ wfcb) {
    int c = blockIdx.x, j = threadIdx.x;
    __shared__ float cin[12];
    __shared__ float h[ED];
    __shared__ float ce[ED];
    __shared__ float red[8];
    if (j < 12) cin[j] = proj[c * 16 + j];
    __syncthreads();
    float v = b1[j];
#pragma unroll
    for (int k = 0; k < 12; k++) v = fmaf(cin[k], w1[k * ED + j], v);
    v = fmaxf(v, 0.f);
    v = ln256(v, g1[j], be1[j], red);
    h[j] = v;
    __syncthreads();
    float u = b2[j];
#pragma unroll 8
    for (int k = 0; k < ED; k++) u = fmaf(h[k], w2[k * ED + j], u);
    u = fmaxf(u, 0.f);
    u = ln256(u, g2[j], be2[j], red);
    ce[j] = u;
    __syncthreads();
    for (int jj = j; jj < JJ; jj += 256) {
        float b = wfcb[jj];
#pragma unroll 8
        for (int k = 0; k < ED; k++) b = fmaf(ce[k], wfcw[k * JJ + jj], b);
        g_B[c * JJ + jj] = b;
    }
}

// ------- kernel 3: keypoints + projection + sample params + compaction --------------
__global__ void __launch_bounds__(256) k_keyproj(
        const float* __restrict__ inst, const float* __restrict__ anchor,
        const float* __restrict__ lfcw, const float* __restrict__ lfcb,
        const float* __restrict__ proj, const float* __restrict__ imwh,
        const float* __restrict__ fixs) {
    int n = blockIdx.x, t = threadIdx.x;
    int wid = t >> 5, lane = t & 31;
    __shared__ float f[ED];
    __shared__ float ls[18];
    __shared__ float kp[13][3];
    __shared__ float anc[11];
    __shared__ float grid[NC * NPTS][2];
    __shared__ int4  t_i[SS];
    __shared__ float4 t_v[SS];
    __shared__ unsigned char fl[SS];
    __shared__ short pos[SS];
    f[t] = inst[n * ED + t];
    if (t < 11) anc[t] = anchor[n * 11 + t];
    __syncthreads();
    // warp-parallel 18-output GEMV: warp w handles outputs w, w+8, w+16
    for (int o = wid; o < 18; o += 8) {
        float v = 0.f;
#pragma unroll
        for (int k = lane; k < ED; k += 32) v = fmaf(f[k], lfcw[k * 18 + o], v);
#pragma unroll
        for (int off = 16; off > 0; off >>= 1) v += __shfl_xor_sync(0xffffffffu, v, off);
        if (lane == 0) ls[o] = 1.f / (1.f + expf(-(v + lfcb[o]))) - 0.5f;
    }
    __syncthreads();
    if (t < 13) {
        float sx = expf(anc[3]), sy = expf(anc[4]), sz = expf(anc[5]);
        float kx, ky, kz;
        if (t < 7) { kx = fixs[t * 3] * sx; ky = fixs[t * 3 + 1] * sy; kz = fixs[t * 3 + 2] * sz; }
        else { int r = t - 7; kx = ls[r * 3] * sx; ky = ls[r * 3 + 1] * sy; kz = ls[r * 3 + 2] * sz; }
        float sn = anc[6], cs = anc[7];
        kp[t][0] = cs * kx - sn * ky + anc[0];
        kp[t][1] = sn * kx + cs * ky + anc[1];
        kp[t][2] = kz + anc[2];
    }
    __syncthreads();
    if (t < NC * NPTS) {
        int c = t / NPTS, p = t % NPTS;
        const float* P = proj + c * 16;
        float x = kp[p][0], y = kp[p][1], z = kp[p][2];
        float r0 = P[0] * x + P[1] * y + P[2] * z + P[3];
        float r1 = P[4] * x + P[5] * y + P[6] * z + P[7];
        float r2 = P[8] * x + P[9] * y + P[10] * z + P[11];
        float zz = fmaxf(r2, 1e-5f);
        grid[t][0] = (r0 / zz) / imwh[c * 2] * 2.f - 1.f;
        grid[t][1] = (r1 / zz) / imwh[c * 2 + 1] * 2.f - 1.f;
    }
    __syncthreads();
    const int Hs[4] = {64, 32, 16, 8}, Ws[4] = {176, 88, 44, 22};
    const int base[4] = {0, 67584, 84480, 88704};
    for (int s = t; s < SS; s += 256) {
        int c = s / (NL * NPTS); int r = s - c * (NL * NPTS);
        int l = r / NPTS, p = r - l * NPTS;
        float gxn = grid[c * NPTS + p][0];
        float gyn = grid[c * NPTS + p][1];
        int H = Hs[l], W = Ws[l];
        float gx = fminf(fmaxf((gxn + 1.f) * (W * 0.5f) - 0.5f, -10000.f), 10000.f);
        float gy = fminf(fmaxf((gyn + 1.f) * (H * 0.5f) - 0.5f, -10000.f), 10000.f);
        float x0f = floorf(gx), y0f = floorf(gy);
        float wx1 = gx - x0f, wy1 = gy - y0f;
        float wx0 = 1.f - wx1, wy0 = 1.f - wy1;
        int x0 = (int)x0f, y0 = (int)y0f;
        int x1 = x0 + 1, y1 = y0 + 1;
        bool vx0 = (x0 >= 0 && x0 < W), vx1 = (x1 >= 0 && x1 < W);
        bool vy0 = (y0 >= 0 && y0 < H), vy1 = (y1 >= 0 && y1 < H);
        int cx0 = min(max(x0, 0), W - 1), cx1 = min(max(x1, 0), W - 1);
        int cy0 = min(max(y0, 0), H - 1), cy1 = min(max(y1, 0), H - 1);
        int pb = base[l] + c * H * W;
        int4 ii;
        ii.x = (pb + cy0 * W + cx0) * ED;
        ii.y = (pb + cy0 * W + cx1) * ED;
        ii.z = (pb + cy1 * W + cx0) * ED;
        ii.w = (pb + cy1 * W + cx1) * ED;
        float4 ww;
        ww.x = wx0 * wy0 * (float)(vx0 && vy0);
        ww.y = wx1 * wy0 * (float)(vx1 && vy0);
        ww.z = wx0 * wy1 * (float)(vx0 && vy1);
        ww.w = wx1 * wy1 * (float)(vx1 && vy1);
        t_i[s] = ii;
        t_v[s] = ww;
        fl[s] = (ww.x + ww.y + ww.z + ww.w) > 0.f ? 1 : 0;
    }
    __syncthreads();
    // deterministic exclusive scan of flags (warp 0, 10 chunks of 32)
    if (t < 32) {
        int run = 0;
        for (int c0 = 0; c0 < SS; c0 += 32) {
            int s = c0 + t;
            int fv = (s < SS) ? (int)fl[s] : 0;
            int x = fv;
#pragma unroll
            for (int o = 1; o < 32; o <<= 1) {
                int y = __shfl_up_sync(0xffffffffu, x, o);
                if (t >= o) x += y;
            }
            if (s < SS) pos[s] = (short)(run + x - fv);
            run += __shfl_sync(0xffffffffu, x, 31);
        }
        if (t == 0) g_cnt[n] = run;
    }
    __syncthreads();
    for (int s = t; s < SS; s += 256) {
        if (fl[s]) {
            int p = pos[s];
            g_ci[n * SS + p] = t_i[s];
            g_cv[n * SS + p] = t_v[s];
            g_cs[n * SS + p] = s;
        }
    }
}

// ------- kernel 4: A[n][j] = (inst+anchor_embed)[n] @ wfc_w  grid(90,2) x 208 -------
#define AB 10
#define JT 208
__global__ void __launch_bounds__(JT) k_A(const float* __restrict__ inst,
                                          const float* __restrict__ aemb,
                                          const float* __restrict__ wfcw) {
    int n0 = blockIdx.x * AB;
    int t = threadIdx.x;
    int j = blockIdx.y * JT + t;
    __shared__ float fs[AB][ED];
    for (int i = t; i < AB * ED; i += JT) {
        int a = i >> 8, k = i & 255;
        fs[a][k] = inst[(n0 + a) * ED + k] + aemb[(n0 + a) * ED + k];
    }
    __syncthreads();
    float acc[AB];
#pragma unroll
    for (int a = 0; a < AB; a++) acc[a] = 0.f;
    for (int k = 0; k < ED; k += 4) {
        float w0 = wfcw[(k + 0) * JJ + j];
        float w1 = wfcw[(k + 1) * JJ + j];
        float w2 = wfcw[(k + 2) * JJ + j];
        float w3 = wfcw[(k + 3) * JJ + j];
#pragma unroll
        for (int a = 0; a < AB; a++) {
            float4 f = *(const float4*)&fs[a][k];
            acc[a] = fmaf(f.x, w0, acc[a]);
            acc[a] = fmaf(f.y, w1, acc[a]);
            acc[a] = fmaf(f.z, w2, acc[a]);
            acc[a] = fmaf(f.w, w3, acc[a]);
        }
    }
#pragma unroll
    for (int a = 0; a < AB; a++) g_A[(n0 + a) * JJ + j] = acc[a];
}

// ------- kernel 5: softmax + warp-per-sample fp16 gather (900 blocks x 256) ---------
__global__ void __launch_bounds__(256) k_fuse(const float* __restrict__ inst,
                                              float* __restrict__ out) {
    int n = blockIdx.x, t = threadIdx.x;
    int wid = t >> 5, lane = t & 31;
    __shared__ float  s_A[JJ];
    __shared__ float  s_B[NC * JJ];
    __shared__ float  s_w[SS * NG];
    __shared__ float  s_cw[SS * NG];
    __shared__ int4   s_ci[SS];
    __shared__ float4 s_cv[SS];
    __shared__ int    s_cs[SS];
    __shared__ float  s_acc[8][ED];
    __shared__ int    s_cnt;
    if (t == 0) s_cnt = g_cnt[n];
    for (int i = t; i < JJ; i += 256) s_A[i] = g_A[n * JJ + i];
    for (int i = t; i < NC * JJ; i += 256) s_B[i] = g_B[i];
    __syncthreads();
    int cnt = s_cnt;
    for (int i = t; i < cnt; i += 256) {
        s_ci[i] = g_ci[n * SS + i];
        s_cv[i] = g_cv[n * SS + i];
        s_cs[i] = g_cs[n * SS + i];
    }

    // --- softmax over 312 samples per group (warp g = group g) ---
    {
        int g = wid;
        float v[10];
        float mx = -1e30f;
#pragma unroll
        for (int i = 0; i < 10; i++) {
            int s = lane + i * 32;
            if (s < SS) {
                int c = s / (NL * NPTS); int r = s - c * (NL * NPTS);
                float val = s_A[r * 8 + g] + s_B[c * JJ + r * 8 + g];
                v[i] = val; mx = fmaxf(mx, val);
            } else v[i] = -1e30f;
        }
#pragma unroll
        for (int o = 16; o > 0; o >>= 1) mx = fmaxf(mx, __shfl_xor_sync(0xffffffffu, mx, o));
        float sum = 0.f;
#pragma unroll
        for (int i = 0; i < 10; i++) {
            v[i] = expf(v[i] - mx);
            if (lane + i * 32 < SS) sum += v[i];
        }
#pragma unroll
        for (int o = 16; o > 0; o >>= 1) sum += __shfl_xor_sync(0xffffffffu, sum, o);
        float inv = 1.f / sum;
#pragma unroll
        for (int i = 0; i < 10; i++) {
            int s = lane + i * 32;
            if (s < SS) s_w[s * NG + g] = v[i] * inv;
        }
    }
    __syncthreads();
    // pre-resolve compacted weights: s_cw[i*NG+g] = s_w[s_cs[i]*NG+g]
    for (int x = t; x < cnt * NG; x += 256) {
        int i = x >> 3, g = x & 7;
        s_cw[x] = s_w[s_cs[i] * NG + g];
    }
    __syncthreads();

    // --- gather: warp w handles compact samples w, w+8, ...; lane = 8 channels ------
    float acc0 = 0.f, acc1 = 0.f, acc2 = 0.f, acc3 = 0.f;
    float acc4 = 0.f, acc5 = 0.f, acc6 = 0.f, acc7 = 0.f;
    int grp = lane >> 2;
    for (int k2 = wid; k2 < cnt; k2 += 8) {
        int4 ii = s_ci[k2];
        float4 ww = s_cv[k2];
        float w = s_cw[k2 * NG + grp];
        float wa = w * ww.x, wb = w * ww.y, wc = w * ww.z, wd = w * ww.w;
        uint4 ua = *((const uint4*)(g_fmapT + ii.x) + lane);
        uint4 ub = *((const uint4*)(g_fmapT + ii.y) + lane);
        uint4 uc = *((const uint4*)(g_fmapT + ii.z) + lane);
        uint4 ud = *((const uint4*)(g_fmapT + ii.w) + lane);
        const __half2* ha = (const __half2*)&ua;
        const __half2* hb = (const __half2*)&ub;
        const __half2* hc = (const __half2*)&uc;
        const __half2* hd = (const __half2*)&ud;
        float2 a0 = __half22float2(ha[0]), a1 = __half22float2(ha[1]);
        float2 a2 = __half22float2(ha[2]), a3 = __half22float2(ha[3]);
        float2 b0 = __half22float2(hb[0]), b1 = __half22float2(hb[1]);
        float2 b2 = __half22float2(hb[2]), b3 = __half22float2(hb[3]);
        float2 c0 = __half22float2(hc[0]), c1 = __half22float2(hc[1]);
        float2 c2 = __half22float2(hc[2]), c3 = __half22float2(hc[3]);
        float2 d0 = __half22float2(hd[0]), d1 = __half22float2(hd[1]);
        float2 d2 = __half22float2(hd[2]), d3 = __half22float2(hd[3]);
        acc0 = fmaf(wa, a0.x, acc0); acc0 = fmaf(wb, b0.x, acc0); acc0 = fmaf(wc, c0.x, acc0); acc0 = fmaf(wd, d0.x, acc0);
        acc1 = fmaf(wa, a0.y, acc1); acc1 = fmaf(wb, b0.y, acc1); acc1 = fmaf(wc, c0.y, acc1); acc1 = fmaf(wd, d0.y, acc1);
        acc2 = fmaf(wa, a1.x, acc2); acc2 = fmaf(wb, b1.x, acc2); acc2 = fmaf(wc, c1.x, acc2); acc2 = fmaf(wd, d1.x, acc2);
        acc3 = fmaf(wa, a1.y, acc3); acc3 = fmaf(wb, b1.y, acc3); acc3 = fmaf(wc, c1.y, acc3); acc3 = fmaf(wd, d1.y, acc3);
        acc4 = fmaf(wa, a2.x, acc4); acc4 = fmaf(wb, b2.x, acc4); acc4 = fmaf(wc, c2.x, acc4); acc4 = fmaf(wd, d2.x, acc4);
        acc5 = fmaf(wa, a2.y, acc5); acc5 = fmaf(wb, b2.y, acc5); acc5 = fmaf(wc, c2.y, acc5); acc5 = fmaf(wd, d2.y, acc5);
        acc6 = fmaf(wa, a3.x, acc6); acc6 = fmaf(wb, b3.x, acc6); acc6 = fmaf(wc, c3.x, acc6); acc6 = fmaf(wd, d3.x, acc6);
        acc7 = fmaf(wa, a3.y, acc7); acc7 = fmaf(wb, b3.y, acc7); acc7 = fmaf(wc, c3.y, acc7); acc7 = fmaf(wd, d3.y, acc7);
    }
    {
        float4* dst = (float4*)&s_acc[wid][lane * 8];
        dst[0] = make_float4(acc0, acc1, acc2, acc3);
        dst[1] = make_float4(acc4, acc5, acc6, acc7);
    }
    __syncthreads();
    float fs = 0.f;
#pragma unroll
    for (int w = 0; w < 8; w++) fs += s_acc[w][t];
    g_fused[n * ED + t] = fs;
    out[(size_t)n * 2 * ED + ED + t] = inst[n * ED + t];
}

// ------- kernel 6: batched output GEMM  grid(75,2) x 128, 12 anchors each ----------
#define OB 12
#define OT 128
__global__ void __launch_bounds__(OT) k_out(const float* __restrict__ opw,
                                            const float* __restrict__ opb,
                                            float* __restrict__ out) {
    int n0 = blockIdx.x * OB;
    int t = threadIdx.x;
    int j = blockIdx.y * OT + t;
    __shared__ float fs[OB][ED];
    for (int i = t; i < OB * ED; i += OT) {
        int a = i >> 8, k = i & 255;
        fs[a][k] = g_fused[(n0 + a) * ED + k];
    }
    __syncthreads();
    float acc[OB];
    float bj = opb[j];
#pragma unroll
    for (int a = 0; a < OB; a++) acc[a] = bj;
    for (int k = 0; k < ED; k += 4) {
        float w0 = opw[(k + 0) * ED + j];
        float w1 = opw[(k + 1) * ED + j];
        float w2 = opw[(k + 2) * ED + j];
        float w3 = opw[(k + 3) * ED + j];
#pragma unroll
        for (int a = 0; a < OB; a++) {
            float4 f = *(const float4*)&fs[a][k];
            acc[a] = fmaf(f.x, w0, acc[a]);
            acc[a] = fmaf(f.y, w1, acc[a]);
            acc[a] = fmaf(f.z, w2, acc[a]);
            acc[a] = fmaf(f.w, w3, acc[a]);
        }
    }
#pragma unroll
    for (int a = 0; a < OB; a++) out[(size_t)(n0 + a) * 2 * ED + j] = acc[a];
}

// ---------------- launch ----------------
extern "C" void kernel_launch(void* const* d_in, const int* in_sizes, int n_in,
                              void* d_out, int out_size) {
    const float* inst  = (const float*)d_in[0];
    const float* anch  = (const float*)d_in[1];
    const float* aemb  = (const float*)d_in[2];
    const float* fm0   = (const float*)d_in[3];
    const float* fm1   = (const float*)d_in[4];
    const float* fm2   = (const float*)d_in[5];
    const float* fm3   = (const float*)d_in[6];
    const float* proj  = (const float*)d_in[7];
    const float* imwh  = (const float*)d_in[8];
    const float* fixs  = (const float*)d_in[9];
    const float* lfcw  = (const float*)d_in[10];
    const float* lfcb  = (const float*)d_in[11];
    const float* cw1   = (const float*)d_in[12];
    const float* cb1   = (const float*)d_in[13];
    const float* cg1   = (const float*)d_in[14];
    const float* cbe1  = (const float*)d_in[15];
    const float* cw2   = (const float*)d_in[16];
    const float* cb2   = (const float*)d_in[17];
    const float* cg2   = (const float*)d_in[18];
    const float* cbe2  = (const float*)d_in[19];
    const float* wfcw  = (const float*)d_in[20];
    const float* wfcb  = (const float*)d_in[21];
    const float* opw   = (const float*)d_in[22];
    const float* opb   = (const float*)d_in[23];
    float* out = (float*)d_out;

    k_transpose<<<dim3(468, 8, 6), dim3(32, 8)>>>(fm0, fm1, fm2, fm3);
    k_cam<<<NC, 256>>>(proj, cw1, cb1, cg1, cbe1, cw2, cb2, cg2, cbe2, wfcw, wfcb);
    k_keyproj<<<NA, 256>>>(inst, anch, lfcw, lfcb, proj, imwh, fixs);
    k_A<<<dim3(NA / AB, 2), JT>>>(inst, aemb, wfcw);
    k_fuse<<<NA, 256>>>(inst, out);
    k_out<<<dim3(NA / OB, 2), OT>>>(opw, opb, out);
}